// round 13
// baseline (speedup 1.0000x reference)
#include <cuda_runtime.h>
#include <cuda_bf16.h>
#include <cstdint>

// Problem constants
#define BB    2
#define TT    2048
#define DD    1024
#define HH    16
#define DH    64
#define BT    (BB*TT)          // 4096
#define KBIG  3072             // 3 * DD (split-in-K bf16 GEMM)
#define NELE  ((size_t)BT*DD)  // 4,194,304

// ---------------------------------------------------------------------------
// Scratch (no cudaMalloc allowed -> __device__ globals)
// ---------------------------------------------------------------------------
__device__ float g_qpre[NELE];
__device__ float g_kpre[NELE];
__device__ float g_vpre[NELE];
__device__ float g_gpre[NELE];
__device__ float g_qn[NELE];
__device__ float g_kn[NELE];
__device__ float g_vn[NELE];
__device__ float g_o[NELE];
__device__ float g_beta[BT*HH];

// bf16 split operands for tensor-core GEMMs
__device__ __align__(16) __nv_bfloat16 g_Ax[(size_t)BT*KBIG];      // [Ah|Al|Ah] of x
__device__ __align__(16) __nv_bfloat16 g_Ao[(size_t)BT*KBIG];      // [Ah|Al|Ah] of o*gate
__device__ __align__(16) __nv_bfloat16 g_Bw[5][(size_t)DD*KBIG];   // W^T splits: [Bh|Bh|Bl]

// ---------------------------------------------------------------------------
// Small helpers
// ---------------------------------------------------------------------------
__device__ __forceinline__ uint32_t smem_u32(const void* p) {
    uint32_t a;
    asm("{ .reg .u64 t; cvta.to.shared.u64 t, %1; cvt.u32.u64 %0, t; }"
        : "=r"(a) : "l"(p));
    return a;
}
__device__ __forceinline__ unsigned sw128(unsigned o) { return o ^ ((o >> 3) & 0x70); }
__device__ __forceinline__ void cpa16(unsigned dst, const void* src) {
    asm volatile("cp.async.cg.shared.global [%0], [%1], 16;\n" ::"r"(dst), "l"(src));
}
__device__ __forceinline__ void ldsm4(uint32_t* r, uint32_t addr) {
    asm volatile("ldmatrix.sync.aligned.m8n8.x4.shared.b16 {%0,%1,%2,%3}, [%4];"
                 : "=r"(r[0]), "=r"(r[1]), "=r"(r[2]), "=r"(r[3]) : "r"(addr));
}
__device__ __forceinline__ void mma_bf16(float* d, const uint32_t* a, const uint32_t* b) {
    asm volatile(
        "mma.sync.aligned.m16n8k16.row.col.f32.bf16.bf16.f32 "
        "{%0,%1,%2,%3}, {%4,%5,%6,%7}, {%8,%9}, {%0,%1,%2,%3};"
        : "+f"(d[0]), "+f"(d[1]), "+f"(d[2]), "+f"(d[3])
        : "r"(a[0]), "r"(a[1]), "r"(a[2]), "r"(a[3]), "r"(b[0]), "r"(b[1]));
}

// ---------------------------------------------------------------------------
// Split kernels: x -> g_Ax ([hi|lo|hi]),  W -> W^T splits ([hi|hi|lo])
// ---------------------------------------------------------------------------
__global__ __launch_bounds__(256) void split_x(const float* __restrict__ x) {
    int row = blockIdx.x;
    int c0  = threadIdx.x * 4;
    float4 v = *(const float4*)(x + (size_t)row * DD + c0);
    float vv[4] = {v.x, v.y, v.z, v.w};
    size_t b = (size_t)row * KBIG + c0;
#pragma unroll
    for (int j = 0; j < 4; j++) {
        __nv_bfloat16 hi = __float2bfloat16(vv[j]);
        __nv_bfloat16 lo = __float2bfloat16(vv[j] - __bfloat162float(hi));
        g_Ax[b + j]          = hi;
        g_Ax[b + DD + j]     = lo;
        g_Ax[b + 2 * DD + j] = hi;
    }
}

__global__ __launch_bounds__(1024) void split_w(const float* __restrict__ Wq,
                                                const float* __restrict__ Wk,
                                                const float* __restrict__ Wv,
                                                const float* __restrict__ Wg,
                                                const float* __restrict__ Wo) {
    const float* W;
    switch (blockIdx.z) {
        case 0: W = Wq; break;
        case 1: W = Wk; break;
        case 2: W = Wv; break;
        case 3: W = Wg; break;
        default: W = Wo; break;
    }
    __nv_bfloat16* Bt = g_Bw[blockIdx.z];
    __shared__ float tile[32][33];
    int tx = threadIdx.x, ty = threadIdx.y;
    int k = blockIdx.y * 32 + ty, n = blockIdx.x * 32 + tx;
    tile[ty][tx] = W[(size_t)k * DD + n];
    __syncthreads();
    int nn = blockIdx.x * 32 + ty, kk = blockIdx.y * 32 + tx;
    float v = tile[tx][ty];  // = W[kk][nn]
    __nv_bfloat16 hi = __float2bfloat16(v);
    __nv_bfloat16 lo = __float2bfloat16(v - __bfloat162float(hi));
    size_t b = (size_t)nn * KBIG + kk;
    Bt[b]          = hi;
    Bt[b + DD]     = hi;
    Bt[b + 2 * DD] = lo;
}

// ---------------------------------------------------------------------------
// bf16 tensor-core GEMM via mma.sync (portable HMMA; tcgen05 PTX rejected by
// this harness's .target sm_103).
// C[M,N] = A[M,KBIG] * Bt[N,KBIG]^T, fp32 out.
// CTA tile 128x256, BK=64, SW128 smem rows, 3-stage cp.async ring.
// 8 warps: warp grid 2(M) x 4(N), warp tile 64x64 (smem-read/FLOP = 0.031).
// ---------------------------------------------------------------------------
#define GBM   128
#define GBN   256
#define GBK   64
#define NSTG  3
#define NS    (KBIG/GBK)            // 48
#define STG_A (GBM*128)             // 16384 B
#define STG_B (GBN*128)             // 32768 B
#define STG_BYTES (STG_A + STG_B)   // 49152 B
#define DSM_BYTES (NSTG*STG_BYTES + 1024)

__device__ __forceinline__ void gemm_mma_body(const __nv_bfloat16* __restrict__ A,
                                              const __nv_bfloat16* __restrict__ Bt,
                                              float* __restrict__ C) {
    extern __shared__ char dynsm[];
    const uint32_t smb = (smem_u32(dynsm) + 1023u) & ~1023u;
    const int tid = threadIdx.x;
    const int wid = tid >> 5, lid = tid & 31;
    const int bm = blockIdx.y * GBM;
    const int bn = blockIdx.x * GBN;
    const int wm = (wid & 1) * 64;   // warp M offset in tile
    const int wn = (wid >> 1) * 64;  // warp N offset in tile

    float acc[4][8][4];
#pragma unroll
    for (int i = 0; i < 4; i++)
#pragma unroll
        for (int j = 0; j < 8; j++)
#pragma unroll
            for (int q = 0; q < 4; q++) acc[i][j][q] = 0.f;

    auto load_stage = [&](int st, int slot) {
        unsigned baseA = smb + slot * STG_BYTES;
        unsigned baseB = baseA + STG_A;
        const __nv_bfloat16* Ab = A + (size_t)bm * KBIG + st * GBK;
        const __nv_bfloat16* Bb = Bt + (size_t)bn * KBIG + st * GBK;
#pragma unroll
        for (int c = tid; c < 1024; c += 256) {
            int r = c >> 3, ci = c & 7;
            cpa16(baseA + sw128(r * 128 + ci * 16), Ab + (size_t)r * KBIG + ci * 8);
        }
#pragma unroll
        for (int c = tid; c < 2048; c += 256) {
            int r = c >> 3, ci = c & 7;
            cpa16(baseB + sw128(r * 128 + ci * 16), Bb + (size_t)r * KBIG + ci * 8);
        }
    };

    // ldmatrix lane-address components (verified layout from R12)
    const int a_row = (lid & 15);
    const int a_kb  = (lid >> 4) * 16;
    const int b_row = (lid & 7) + (lid >> 4) * 8;
    const int b_kb  = ((lid >> 3) & 1) * 16;

    load_stage(0, 0);
    asm volatile("cp.async.commit_group;\n" ::: "memory");
    load_stage(1, 1);
    asm volatile("cp.async.commit_group;\n" ::: "memory");

    for (int i = 0; i < NS; i++) {
        const int slot = i % NSTG;
        asm volatile("cp.async.wait_group 1;\n" ::: "memory");
        __syncthreads();

        const unsigned baseA = smb + slot * STG_BYTES;
        const unsigned baseB = baseA + STG_A;

#pragma unroll
        for (int ks = 0; ks < 4; ks++) {
            uint32_t af[4][4];
#pragma unroll
            for (int mt = 0; mt < 4; mt++)
                ldsm4(af[mt],
                      baseA + sw128((wm + mt * 16 + a_row) * 128 + ks * 32 + a_kb));
            uint32_t bfr[4][4];
#pragma unroll
            for (int nt = 0; nt < 4; nt++)
                ldsm4(bfr[nt],
                      baseB + sw128((wn + nt * 16 + b_row) * 128 + ks * 32 + b_kb));
#pragma unroll
            for (int mt = 0; mt < 4; mt++)
#pragma unroll
                for (int n8 = 0; n8 < 8; n8++)
                    mma_bf16(acc[mt][n8], af[mt], &bfr[n8 >> 1][(n8 & 1) * 2]);
        }

        __syncthreads();
        if (i + 2 < NS) load_stage(i + 2, (i + 2) % NSTG);
        asm volatile("cp.async.commit_group;\n" ::: "memory");
    }

    // Epilogue
    const int g   = lid >> 2;
    const int tig = lid & 3;
#pragma unroll
    for (int mt = 0; mt < 4; mt++) {
#pragma unroll
        for (int n8 = 0; n8 < 8; n8++) {
            int row = bm + wm + mt * 16 + g;
            int col = bn + wn + n8 * 8 + tig * 2;
            float2 lo = make_float2(acc[mt][n8][0], acc[mt][n8][1]);
            float2 hi = make_float2(acc[mt][n8][2], acc[mt][n8][3]);
            *(float2*)(C + (size_t)row * DD + col)       = lo;
            *(float2*)(C + (size_t)(row + 8) * DD + col) = hi;
        }
    }
}

__global__ __launch_bounds__(256, 1) void proj_mma() {
    float* C;
    switch (blockIdx.z) {
        case 0:  C = g_qpre; break;
        case 1:  C = g_kpre; break;
        case 2:  C = g_vpre; break;
        default: C = g_gpre; break;
    }
    gemm_mma_body(g_Ax, g_Bw[blockIdx.z], C);
}

__global__ __launch_bounds__(256, 1) void out_mma(float* __restrict__ out) {
    gemm_mma_body(g_Ao, g_Bw[4], out);
}

// ---------------------------------------------------------------------------
// beta = sigmoid(x @ Wb): Wb staged in smem (2 K-passes), one thread per row.
// grid 32 x 128 threads: thread handles full row, 16 accumulators.
// ---------------------------------------------------------------------------
__global__ __launch_bounds__(128) void beta_kernel(const float* __restrict__ x,
                                                   const float* __restrict__ Wb) {
    __shared__ float wbs[512][16];  // 32 KB
    int row = blockIdx.x * 128 + threadIdx.x;
    const float4* xr = (const float4*)(x + (size_t)row * DD);

    float acc[16];
#pragma unroll
    for (int h = 0; h < 16; h++) acc[h] = 0.f;

#pragma unroll
    for (int pass = 0; pass < 2; pass++) {
        if (pass) __syncthreads();
        // load 512x16 = 2048 float4 by 128 threads
        for (int i = threadIdx.x; i < 2048; i += 128) {
            int r = i >> 2, c = (i & 3) * 4;
            *(float4*)&wbs[r][c] =
                *(const float4*)(Wb + (size_t)(pass * 512 + r) * 16 + c);
        }
        __syncthreads();
#pragma unroll 4
        for (int kc = 0; kc < 128; kc++) {
            float4 xv = xr[pass * 128 + kc];
            float xa[4] = {xv.x, xv.y, xv.z, xv.w};
#pragma unroll
            for (int j = 0; j < 4; j++) {
                const float* wr = wbs[kc * 4 + j];
#pragma unroll
                for (int h = 0; h < 16; h++) acc[h] = fmaf(xa[j], wr[h], acc[h]);
            }
        }
    }
#pragma unroll
    for (int h = 0; h < 16; h++)
        g_beta[(size_t)row * HH + h] = 1.f / (1.f + expf(-acc[h]));
}

// ---------------------------------------------------------------------------
// Depthwise causal conv(k=4) + bias + silu, then (for q,k) per-head l2norm.
// ---------------------------------------------------------------------------
__global__ __launch_bounds__(256) void conv_norm(const float* __restrict__ cw,
                                                 const float* __restrict__ cb,
                                                 int mode) {
    const float* pre = (mode == 0) ? g_qpre : (mode == 1) ? g_kpre : g_vpre;
    float* out       = (mode == 0) ? g_qn   : (mode == 1) ? g_kn   : g_vn;
    int blk = blockIdx.x;
    int hq  = blk & 3;
    int bt  = blk >> 2;
    int t   = bt & (TT - 1);
    int b   = bt >> 11;
    int tid = threadIdx.x;
    int hh  = tid >> 6;
    int ch  = hq * 256 + tid;

    float acc = cb[ch];
#pragma unroll
    for (int j = 0; j < 4; j++) {
        int tt = t - 3 + j;
        if (tt >= 0)
            acc = fmaf(pre[(size_t)(b * TT + tt) * DD + ch], cw[ch * 4 + j], acc);
    }
    float y = acc / (1.f + expf(-acc));  // silu

    if (mode < 2) {
        float ss = y * y;
#pragma unroll
        for (int m = 16; m; m >>= 1) ss += __shfl_xor_sync(0xffffffffu, ss, m);
        __shared__ float red[8];
        if ((tid & 31) == 0) red[tid >> 5] = ss;
        __syncthreads();
        float tot = red[hh * 2] + red[hh * 2 + 1];
        float inv = rsqrtf(tot + 1e-6f);
        if (mode == 0) inv *= 0.125f;
        y *= inv;
    }
    out[(size_t)bt * DD + ch] = y;
}

// ---------------------------------------------------------------------------
// Sequential delta-rule scan. Triple-buffered cp.async, ONE barrier per step
// (slot written at step t == slot last read at t-1, ordered by this step's bar).
// ---------------------------------------------------------------------------
__device__ __forceinline__ void cpa4(void* smem, const void* g) {
    unsigned sa = (unsigned)__cvta_generic_to_shared(smem);
    asm volatile("cp.async.ca.shared.global [%0], [%1], 4;\n" ::"r"(sa), "l"(g));
}

__global__ __launch_bounds__(256) void scan_kernel() {
    int blk = blockIdx.x;
    int sv  = blk & 3;
    int bh  = blk >> 2;
    int b   = bh >> 4, h = bh & 15;
    int v0  = sv * 16;
    int tid = threadIdx.x;
    int g   = tid & 15;
    int vl  = tid >> 4;

    __shared__ __align__(16) float buf[3][160];

    const size_t base = (size_t)b * TT * DD + h * DH;
    const float* Kp = g_kn + base;
    const float* Qp = g_qn + base;
    const float* Vp = g_vn + base + v0;
    const float* Bp = g_beta + (size_t)b * TT * HH + h;
    float* Op = g_o + base + v0;

    auto issue = [&](int t, int pb) {
        if (tid < 64)        cpa4(&buf[pb][tid], Kp + (size_t)t * DD + tid);
        else if (tid < 128)  cpa4(&buf[pb][tid], Qp + (size_t)t * DD + (tid - 64));
        else if (tid < 144)  cpa4(&buf[pb][tid], Vp + (size_t)t * DD + (tid - 128));
        else if (tid == 144) cpa4(&buf[pb][144], Bp + (size_t)t * HH);
    };

    issue(0, 0);
    asm volatile("cp.async.commit_group;\n" ::: "memory");
    issue(1, 1);
    asm volatile("cp.async.commit_group;\n" ::: "memory");

    float s0 = 0.f, s1 = 0.f, s2 = 0.f, s3 = 0.f;
    int pb = 0;

    for (int t = 0; t < TT; t++) {
        asm volatile("cp.async.wait_group 1;\n" ::: "memory");
        __syncthreads();

        float4 kv = *(const float4*)&buf[pb][g * 4];
        float4 qv = *(const float4*)&buf[pb][64 + g * 4];
        float  vt = buf[pb][128 + vl];
        float  bt = buf[pb][144];

        float p = fmaf(kv.x, s0, fmaf(kv.y, s1, fmaf(kv.z, s2, kv.w * s3)));
        p += __shfl_xor_sync(0xffffffffu, p, 1);
        p += __shfl_xor_sync(0xffffffffu, p, 2);
        p += __shfl_xor_sync(0xffffffffu, p, 4);
        p += __shfl_xor_sync(0xffffffffu, p, 8);

        float err = (vt - p) * bt;
        s0 = fmaf(kv.x, err, s0);
        s1 = fmaf(kv.y, err, s1);
        s2 = fmaf(kv.z, err, s2);
        s3 = fmaf(kv.w, err, s3);

        float o = fmaf(qv.x, s0, fmaf(qv.y, s1, fmaf(qv.z, s2, qv.w * s3)));
        o += __shfl_xor_sync(0xffffffffu, o, 1);
        o += __shfl_xor_sync(0xffffffffu, o, 2);
        o += __shfl_xor_sync(0xffffffffu, o, 4);
        o += __shfl_xor_sync(0xffffffffu, o, 8);
        if (g == 0) Op[(size_t)t * DD + vl] = o;

        // write slot (t+2)%3 == slot of step t-1: its readers passed this
        // step's __syncthreads already -> safe without a second barrier.
        if (t + 2 < TT) issue(t + 2, (t + 2) % 3);
        asm volatile("cp.async.commit_group;\n" ::: "memory");

        pb = (pb == 2) ? 0 : pb + 1;
    }
}

// ---------------------------------------------------------------------------
// RMSNorm over head_dim + silu gate -> bf16 split rows of g_Ao
// ---------------------------------------------------------------------------
__global__ __launch_bounds__(256) void norm_gate(const float* __restrict__ nw) {
    int blk = blockIdx.x;
    int hq  = blk & 3;
    int bt  = blk >> 2;
    int tid = threadIdx.x;
    int hh  = tid >> 6;
    int c   = tid & 63;
    int ch  = hq * 256 + tid;
    size_t idx = (size_t)bt * DD + ch;

    float o  = g_o[idx];
    float ss = o * o;
#pragma unroll
    for (int m = 16; m; m >>= 1) ss += __shfl_xor_sync(0xffffffffu, ss, m);
    __shared__ float red[8];
    if ((tid & 31) == 0) red[tid >> 5] = ss;
    __syncthreads();
    float tot = red[hh * 2] + red[hh * 2 + 1];
    float inv = rsqrtf(tot * (1.f / 64.f) + 1e-5f);
    o *= inv * nw[c];
    float gt = g_gpre[idx];
    o *= gt / (1.f + expf(-gt));

    __nv_bfloat16 hi = __float2bfloat16(o);
    __nv_bfloat16 lo = __float2bfloat16(o - __bfloat162float(hi));
    size_t b = (size_t)bt * KBIG + ch;
    g_Ao[b]          = hi;
    g_Ao[b + DD]     = lo;
    g_Ao[b + 2 * DD] = hi;
}

// ---------------------------------------------------------------------------
// Launch: x Wq Wk Wv Wo Wg Wb cq_w cq_b ck_w ck_b cv_w cv_b nw
// ---------------------------------------------------------------------------
extern "C" void kernel_launch(void* const* d_in, const int* in_sizes, int n_in,
                              void* d_out, int out_size) {
    const float* x    = (const float*)d_in[0];
    const float* Wq   = (const float*)d_in[1];
    const float* Wk   = (const float*)d_in[2];
    const float* Wv   = (const float*)d_in[3];
    const float* Wo   = (const float*)d_in[4];
    const float* Wg   = (const float*)d_in[5];
    const float* Wb   = (const float*)d_in[6];
    const float* cq_w = (const float*)d_in[7];
    const float* cq_b = (const float*)d_in[8];
    const float* ck_w = (const float*)d_in[9];
    const float* ck_b = (const float*)d_in[10];
    const float* cv_w = (const float*)d_in[11];
    const float* cv_b = (const float*)d_in[12];
    const float* nw   = (const float*)d_in[13];
    float* out = (float*)d_out;

    cudaFuncSetAttribute(proj_mma, cudaFuncAttributeMaxDynamicSharedMemorySize, DSM_BYTES);
    cudaFuncSetAttribute(out_mma,  cudaFuncAttributeMaxDynamicSharedMemorySize, DSM_BYTES);

    split_x<<<BT, 256>>>(x);
    split_w<<<dim3(32, 32, 5), dim3(32, 32)>>>(Wq, Wk, Wv, Wg, Wo);

    proj_mma<<<dim3(DD / GBN, BT / GBM, 4), 256, DSM_BYTES>>>();

    beta_kernel<<<BT / 128, 128>>>(x, Wb);
    conv_norm<<<BT * 4, 256>>>(cq_w, cq_b, 0);
    conv_norm<<<BT * 4, 256>>>(ck_w, ck_b, 1);
    conv_norm<<<BT * 4, 256>>>(cv_w, cv_b, 2);
    scan_kernel<<<BB * HH * 4, 256>>>();
    norm_gate<<<BT * 4, 256>>>(nw);

    out_mma<<<dim3(DD / GBN, BT / GBM), 256, DSM_BYTES>>>(out);
}

// round 14
// speedup vs baseline: 1.0797x; 1.0797x over previous
#include <cuda_runtime.h>
#include <cuda_bf16.h>
#include <cstdint>

// Problem constants
#define BB    2
#define TT    2048
#define DD    1024
#define HH    16
#define DH    64
#define BT    (BB*TT)          // 4096
#define KBIG  3072             // 3 * DD (split-in-K bf16 GEMM)
#define NELE  ((size_t)BT*DD)  // 4,194,304

// ---------------------------------------------------------------------------
// Scratch (no cudaMalloc allowed -> __device__ globals)
// ---------------------------------------------------------------------------
__device__ float g_qpre[NELE];
__device__ float g_kpre[NELE];
__device__ float g_vpre[NELE];
__device__ float g_gpre[NELE];
__device__ float g_qn[NELE];
__device__ float g_kn[NELE];
__device__ float g_vn[NELE];
__device__ float g_o[NELE];
__device__ float g_beta[BT*HH];

// bf16 split operands for tensor-core GEMMs
__device__ __align__(16) __nv_bfloat16 g_Ax[(size_t)BT*KBIG];      // [Ah|Al|Ah] of x
__device__ __align__(16) __nv_bfloat16 g_Ao[(size_t)BT*KBIG];      // [Ah|Al|Ah] of o*gate
__device__ __align__(16) __nv_bfloat16 g_Bw[5][(size_t)DD*KBIG];   // W^T splits: [Bh|Bh|Bl]

// ---------------------------------------------------------------------------
// Small helpers
// ---------------------------------------------------------------------------
__device__ __forceinline__ uint32_t smem_u32(const void* p) {
    uint32_t a;
    asm("{ .reg .u64 t; cvta.to.shared.u64 t, %1; cvt.u32.u64 %0, t; }"
        : "=r"(a) : "l"(p));
    return a;
}
__device__ __forceinline__ unsigned sw128(unsigned o) { return o ^ ((o >> 3) & 0x70); }
__device__ __forceinline__ void cpa16(unsigned dst, const void* src) {
    asm volatile("cp.async.cg.shared.global [%0], [%1], 16;\n" ::"r"(dst), "l"(src));
}
__device__ __forceinline__ void ldsm4(uint32_t* r, uint32_t addr) {
    asm volatile("ldmatrix.sync.aligned.m8n8.x4.shared.b16 {%0,%1,%2,%3}, [%4];"
                 : "=r"(r[0]), "=r"(r[1]), "=r"(r[2]), "=r"(r[3]) : "r"(addr));
}
__device__ __forceinline__ void mma_bf16(float* d, const uint32_t* a, const uint32_t* b) {
    asm volatile(
        "mma.sync.aligned.m16n8k16.row.col.f32.bf16.bf16.f32 "
        "{%0,%1,%2,%3}, {%4,%5,%6,%7}, {%8,%9}, {%0,%1,%2,%3};"
        : "+f"(d[0]), "+f"(d[1]), "+f"(d[2]), "+f"(d[3])
        : "r"(a[0]), "r"(a[1]), "r"(a[2]), "r"(a[3]), "r"(b[0]), "r"(b[1]));
}

// ---------------------------------------------------------------------------
// Split kernels: x -> g_Ax ([hi|lo|hi]),  W -> W^T splits ([hi|hi|lo])
// ---------------------------------------------------------------------------
__global__ __launch_bounds__(256) void split_x(const float* __restrict__ x) {
    int row = blockIdx.x;
    int c0  = threadIdx.x * 4;
    float4 v = *(const float4*)(x + (size_t)row * DD + c0);
    float vv[4] = {v.x, v.y, v.z, v.w};
    size_t b = (size_t)row * KBIG + c0;
#pragma unroll
    for (int j = 0; j < 4; j++) {
        __nv_bfloat16 hi = __float2bfloat16(vv[j]);
        __nv_bfloat16 lo = __float2bfloat16(vv[j] - __bfloat162float(hi));
        g_Ax[b + j]          = hi;
        g_Ax[b + DD + j]     = lo;
        g_Ax[b + 2 * DD + j] = hi;
    }
}

__global__ __launch_bounds__(1024) void split_w(const float* __restrict__ Wq,
                                                const float* __restrict__ Wk,
                                                const float* __restrict__ Wv,
                                                const float* __restrict__ Wg,
                                                const float* __restrict__ Wo) {
    const float* W;
    switch (blockIdx.z) {
        case 0: W = Wq; break;
        case 1: W = Wk; break;
        case 2: W = Wv; break;
        case 3: W = Wg; break;
        default: W = Wo; break;
    }
    __nv_bfloat16* Bt = g_Bw[blockIdx.z];
    __shared__ float tile[32][33];
    int tx = threadIdx.x, ty = threadIdx.y;
    int k = blockIdx.y * 32 + ty, n = blockIdx.x * 32 + tx;
    tile[ty][tx] = W[(size_t)k * DD + n];
    __syncthreads();
    int nn = blockIdx.x * 32 + ty, kk = blockIdx.y * 32 + tx;
    float v = tile[tx][ty];  // = W[kk][nn]
    __nv_bfloat16 hi = __float2bfloat16(v);
    __nv_bfloat16 lo = __float2bfloat16(v - __bfloat162float(hi));
    size_t b = (size_t)nn * KBIG + kk;
    Bt[b]          = hi;
    Bt[b + DD]     = hi;
    Bt[b + 2 * DD] = lo;
}

// ---------------------------------------------------------------------------
// bf16 tensor-core GEMM via mma.sync (portable HMMA; tcgen05 PTX rejected by
// this harness's .target sm_103).
// C[M,N] = A[M,KBIG] * Bt[N,KBIG]^T, fp32 out.
// CTA tile 128x128 (R12-verified), BK=64, SW128 smem, 3-stage cp.async ring.
// __launch_bounds__(256,2): cap regs at 128 -> 2 CTAs/SM (2x99KB smem fits).
// ---------------------------------------------------------------------------
#define GBM   128
#define GBN   128
#define GBK   64
#define NSTG  3
#define NS    (KBIG/GBK)            // 48
#define STG_A (GBM*128)             // 16384 B
#define STG_B (GBN*128)             // 16384 B
#define STG_BYTES (STG_A + STG_B)   // 32768 B
#define DSM_BYTES (NSTG*STG_BYTES + 1024)

__device__ __forceinline__ void gemm_mma_body(const __nv_bfloat16* __restrict__ A,
                                              const __nv_bfloat16* __restrict__ Bt,
                                              float* __restrict__ C) {
    extern __shared__ char dynsm[];
    const uint32_t smb = (smem_u32(dynsm) + 1023u) & ~1023u;
    const int tid = threadIdx.x;
    const int wid = tid >> 5, lid = tid & 31;
    const int bm = blockIdx.y * GBM;
    const int bn = blockIdx.x * GBN;
    const int wm = (wid & 3) * 32;   // warp M offset in tile
    const int wn = (wid >> 2) * 64;  // warp N offset in tile

    float acc[2][8][4];
#pragma unroll
    for (int i = 0; i < 2; i++)
#pragma unroll
        for (int j = 0; j < 8; j++)
#pragma unroll
            for (int q = 0; q < 4; q++) acc[i][j][q] = 0.f;

    auto load_stage = [&](int st, int slot) {
        unsigned baseA = smb + slot * STG_BYTES;
        unsigned baseB = baseA + STG_A;
        const __nv_bfloat16* Ab = A + (size_t)bm * KBIG + st * GBK;
        const __nv_bfloat16* Bb = Bt + (size_t)bn * KBIG + st * GBK;
#pragma unroll
        for (int c = tid; c < 1024; c += 256) {
            int r = c >> 3, ci = c & 7;
            cpa16(baseA + sw128(r * 128 + ci * 16), Ab + (size_t)r * KBIG + ci * 8);
        }
#pragma unroll
        for (int c = tid; c < 1024; c += 256) {
            int r = c >> 3, ci = c & 7;
            cpa16(baseB + sw128(r * 128 + ci * 16), Bb + (size_t)r * KBIG + ci * 8);
        }
    };

    // ldmatrix lane-address components (verified layout from R12)
    const int a_row = (lid & 15);
    const int a_kb  = (lid >> 4) * 16;
    const int b_row = (lid & 7) + (lid >> 4) * 8;
    const int b_kb  = ((lid >> 3) & 1) * 16;

    load_stage(0, 0);
    asm volatile("cp.async.commit_group;\n" ::: "memory");
    load_stage(1, 1);
    asm volatile("cp.async.commit_group;\n" ::: "memory");

    for (int i = 0; i < NS; i++) {
        const int slot = i % NSTG;
        asm volatile("cp.async.wait_group 1;\n" ::: "memory");
        __syncthreads();

        const unsigned baseA = smb + slot * STG_BYTES;
        const unsigned baseB = baseA + STG_A;

#pragma unroll
        for (int ks = 0; ks < 4; ks++) {
            uint32_t af[2][4];
#pragma unroll
            for (int mt = 0; mt < 2; mt++)
                ldsm4(af[mt],
                      baseA + sw128((wm + mt * 16 + a_row) * 128 + ks * 32 + a_kb));
            uint32_t bfr[4][4];
#pragma unroll
            for (int nt = 0; nt < 4; nt++)
                ldsm4(bfr[nt],
                      baseB + sw128((wn + nt * 16 + b_row) * 128 + ks * 32 + b_kb));
#pragma unroll
            for (int mt = 0; mt < 2; mt++)
#pragma unroll
                for (int n8 = 0; n8 < 8; n8++)
                    mma_bf16(acc[mt][n8], af[mt], &bfr[n8 >> 1][(n8 & 1) * 2]);
        }

        __syncthreads();
        if (i + 2 < NS) load_stage(i + 2, (i + 2) % NSTG);
        asm volatile("cp.async.commit_group;\n" ::: "memory");
    }

    // Epilogue
    const int g   = lid >> 2;
    const int tig = lid & 3;
#pragma unroll
    for (int mt = 0; mt < 2; mt++) {
#pragma unroll
        for (int n8 = 0; n8 < 8; n8++) {
            int row = bm + wm + mt * 16 + g;
            int col = bn + wn + n8 * 8 + tig * 2;
            float2 lo = make_float2(acc[mt][n8][0], acc[mt][n8][1]);
            float2 hi = make_float2(acc[mt][n8][2], acc[mt][n8][3]);
            *(float2*)(C + (size_t)row * DD + col)       = lo;
            *(float2*)(C + (size_t)(row + 8) * DD + col) = hi;
        }
    }
}

__global__ __launch_bounds__(256, 2) void proj_mma() {
    float* C;
    switch (blockIdx.z) {
        case 0:  C = g_qpre; break;
        case 1:  C = g_kpre; break;
        case 2:  C = g_vpre; break;
        default: C = g_gpre; break;
    }
    gemm_mma_body(g_Ax, g_Bw[blockIdx.z], C);
}

__global__ __launch_bounds__(256, 2) void out_mma(float* __restrict__ out) {
    gemm_mma_body(g_Ao, g_Bw[4], out);
}

// ---------------------------------------------------------------------------
// beta = sigmoid(x @ Wb): warp per row (4096 warps = 512 CTAs of 256).
// Lane l accumulates k = l, l+32, ... (coalesced x); Wb row (64B) from L1.
// ---------------------------------------------------------------------------
__global__ __launch_bounds__(256) void beta_kernel(const float* __restrict__ x,
                                                   const float* __restrict__ Wb) {
    int row = (blockIdx.x * 256 + threadIdx.x) >> 5;
    int lid = threadIdx.x & 31;
    const float* xr = x + (size_t)row * DD;

    float acc[16];
#pragma unroll
    for (int h = 0; h < 16; h++) acc[h] = 0.f;

#pragma unroll 4
    for (int i = 0; i < 32; i++) {
        int k = i * 32 + lid;
        float xv = xr[k];
        const float4* wr = (const float4*)(Wb + (size_t)k * 16);
        float4 w0 = wr[0], w1 = wr[1], w2 = wr[2], w3 = wr[3];
        acc[0]  = fmaf(xv, w0.x, acc[0]);
        acc[1]  = fmaf(xv, w0.y, acc[1]);
        acc[2]  = fmaf(xv, w0.z, acc[2]);
        acc[3]  = fmaf(xv, w0.w, acc[3]);
        acc[4]  = fmaf(xv, w1.x, acc[4]);
        acc[5]  = fmaf(xv, w1.y, acc[5]);
        acc[6]  = fmaf(xv, w1.z, acc[6]);
        acc[7]  = fmaf(xv, w1.w, acc[7]);
        acc[8]  = fmaf(xv, w2.x, acc[8]);
        acc[9]  = fmaf(xv, w2.y, acc[9]);
        acc[10] = fmaf(xv, w2.z, acc[10]);
        acc[11] = fmaf(xv, w2.w, acc[11]);
        acc[12] = fmaf(xv, w3.x, acc[12]);
        acc[13] = fmaf(xv, w3.y, acc[13]);
        acc[14] = fmaf(xv, w3.z, acc[14]);
        acc[15] = fmaf(xv, w3.w, acc[15]);
    }
#pragma unroll
    for (int m = 16; m; m >>= 1)
#pragma unroll
        for (int h = 0; h < 16; h++)
            acc[h] += __shfl_xor_sync(0xffffffffu, acc[h], m);
    if (lid < 16)
        g_beta[(size_t)row * HH + lid] = 1.f / (1.f + expf(-acc[lid]));
}

// ---------------------------------------------------------------------------
// Depthwise causal conv(k=4) + bias + silu, then (for q,k) per-head l2norm.
// Fused: blockIdx.z = mode (0=q, 1=k, 2=v) -> single launch, modes overlap.
// ---------------------------------------------------------------------------
__global__ __launch_bounds__(256) void conv_norm(const float* __restrict__ cq_w,
                                                 const float* __restrict__ cq_b,
                                                 const float* __restrict__ ck_w,
                                                 const float* __restrict__ ck_b,
                                                 const float* __restrict__ cv_w,
                                                 const float* __restrict__ cv_b) {
    int mode = blockIdx.z;
    const float* pre = (mode == 0) ? g_qpre : (mode == 1) ? g_kpre : g_vpre;
    float* out       = (mode == 0) ? g_qn   : (mode == 1) ? g_kn   : g_vn;
    const float* cw  = (mode == 0) ? cq_w   : (mode == 1) ? ck_w   : cv_w;
    const float* cb  = (mode == 0) ? cq_b   : (mode == 1) ? ck_b   : cv_b;

    int blk = blockIdx.x;
    int hq  = blk & 3;
    int bt  = blk >> 2;
    int t   = bt & (TT - 1);
    int b   = bt >> 11;
    int tid = threadIdx.x;
    int hh  = tid >> 6;
    int ch  = hq * 256 + tid;

    float acc = cb[ch];
#pragma unroll
    for (int j = 0; j < 4; j++) {
        int tt = t - 3 + j;
        if (tt >= 0)
            acc = fmaf(pre[(size_t)(b * TT + tt) * DD + ch], cw[ch * 4 + j], acc);
    }
    float y = acc / (1.f + expf(-acc));  // silu

    if (mode < 2) {
        float ss = y * y;
#pragma unroll
        for (int m = 16; m; m >>= 1) ss += __shfl_xor_sync(0xffffffffu, ss, m);
        __shared__ float red[8];
        if ((tid & 31) == 0) red[tid >> 5] = ss;
        __syncthreads();
        float tot = red[hh * 2] + red[hh * 2 + 1];
        float inv = rsqrtf(tot + 1e-6f);
        if (mode == 0) inv *= 0.125f;
        y *= inv;
    }
    out[(size_t)bt * DD + ch] = y;
}

// ---------------------------------------------------------------------------
// Sequential delta-rule scan. Triple-buffered cp.async, ONE barrier per step.
// Fused reduction: o_t = q.S_old + (q.k)*err, so p=k.S_old, po=q.S_old,
// qk=q.k are reduced CONCURRENTLY (3 independent shfl chains overlap),
// halving the per-step critical path vs two serial reduction phases.
// ---------------------------------------------------------------------------
__device__ __forceinline__ void cpa4(void* smem, const void* g) {
    unsigned sa = (unsigned)__cvta_generic_to_shared(smem);
    asm volatile("cp.async.ca.shared.global [%0], [%1], 4;\n" ::"r"(sa), "l"(g));
}

__global__ __launch_bounds__(256) void scan_kernel() {
    int blk = blockIdx.x;
    int sv  = blk & 3;
    int bh  = blk >> 2;
    int b   = bh >> 4, h = bh & 15;
    int v0  = sv * 16;
    int tid = threadIdx.x;
    int g   = tid & 15;
    int vl  = tid >> 4;

    __shared__ __align__(16) float buf[3][160];

    const size_t base = (size_t)b * TT * DD + h * DH;
    const float* Kp = g_kn + base;
    const float* Qp = g_qn + base;
    const float* Vp = g_vn + base + v0;
    const float* Bp = g_beta + (size_t)b * TT * HH + h;
    float* Op = g_o + base + v0;

    auto issue = [&](int t, int pb) {
        if (tid < 64)        cpa4(&buf[pb][tid], Kp + (size_t)t * DD + tid);
        else if (tid < 128)  cpa4(&buf[pb][tid], Qp + (size_t)t * DD + (tid - 64));
        else if (tid < 144)  cpa4(&buf[pb][tid], Vp + (size_t)t * DD + (tid - 128));
        else if (tid == 144) cpa4(&buf[pb][144], Bp + (size_t)t * HH);
    };

    issue(0, 0);
    asm volatile("cp.async.commit_group;\n" ::: "memory");
    issue(1, 1);
    asm volatile("cp.async.commit_group;\n" ::: "memory");

    float s0 = 0.f, s1 = 0.f, s2 = 0.f, s3 = 0.f;
    int pb = 0;

    for (int t = 0; t < TT; t++) {
        asm volatile("cp.async.wait_group 1;\n" ::: "memory");
        __syncthreads();

        float4 kv = *(const float4*)&buf[pb][g * 4];
        float4 qv = *(const float4*)&buf[pb][64 + g * 4];
        float  vt = buf[pb][128 + vl];
        float  bt = buf[pb][144];

        // three partial dots, reduced concurrently (independent chains)
        float p  = fmaf(kv.x, s0, fmaf(kv.y, s1, fmaf(kv.z, s2, kv.w * s3)));
        float po = fmaf(qv.x, s0, fmaf(qv.y, s1, fmaf(qv.z, s2, qv.w * s3)));
        float qk = fmaf(qv.x, kv.x, fmaf(qv.y, kv.y,
                        fmaf(qv.z, kv.z, qv.w * kv.w)));
#pragma unroll
        for (int m = 1; m <= 8; m <<= 1) {
            p  += __shfl_xor_sync(0xffffffffu, p,  m);
            po += __shfl_xor_sync(0xffffffffu, po, m);
            qk += __shfl_xor_sync(0xffffffffu, qk, m);
        }

        float err = (vt - p) * bt;
        float o   = fmaf(qk, err, po);
        if (g == 0) Op[(size_t)t * DD + vl] = o;

        s0 = fmaf(kv.x, err, s0);
        s1 = fmaf(kv.y, err, s1);
        s2 = fmaf(kv.z, err, s2);
        s3 = fmaf(kv.w, err, s3);

        // slot (t+2)%3 == slot of step t-1: its readers passed this step's
        // __syncthreads already -> safe without a second barrier.
        if (t + 2 < TT) issue(t + 2, (t + 2) % 3);
        asm volatile("cp.async.commit_group;\n" ::: "memory");

        pb = (pb == 2) ? 0 : pb + 1;
    }
}

// ---------------------------------------------------------------------------
// RMSNorm over head_dim + silu gate -> bf16 split rows of g_Ao
// ---------------------------------------------------------------------------
__global__ __launch_bounds__(256) void norm_gate(const float* __restrict__ nw) {
    int blk = blockIdx.x;
    int hq  = blk & 3;
    int bt  = blk >> 2;
    int tid = threadIdx.x;
    int hh  = tid >> 6;
    int c   = tid & 63;
    int ch  = hq * 256 + tid;
    size_t idx = (size_t)bt * DD + ch;

    float o  = g_o[idx];
    float ss = o * o;
#pragma unroll
    for (int m = 16; m; m >>= 1) ss += __shfl_xor_sync(0xffffffffu, ss, m);
    __shared__ float red[8];
    if ((tid & 31) == 0) red[tid >> 5] = ss;
    __syncthreads();
    float tot = red[hh * 2] + red[hh * 2 + 1];
    float inv = rsqrtf(tot * (1.f / 64.f) + 1e-5f);
    o *= inv * nw[c];
    float gt = g_gpre[idx];
    o *= gt / (1.f + expf(-gt));

    __nv_bfloat16 hi = __float2bfloat16(o);
    __nv_bfloat16 lo = __float2bfloat16(o - __bfloat162float(hi));
    size_t b = (size_t)bt * KBIG + ch;
    g_Ao[b]          = hi;
    g_Ao[b + DD]     = lo;
    g_Ao[b + 2 * DD] = hi;
}

// ---------------------------------------------------------------------------
// Launch: x Wq Wk Wv Wo Wg Wb cq_w cq_b ck_w ck_b cv_w cv_b nw
// ---------------------------------------------------------------------------
extern "C" void kernel_launch(void* const* d_in, const int* in_sizes, int n_in,
                              void* d_out, int out_size) {
    const float* x    = (const float*)d_in[0];
    const float* Wq   = (const float*)d_in[1];
    const float* Wk   = (const float*)d_in[2];
    const float* Wv   = (const float*)d_in[3];
    const float* Wo   = (const float*)d_in[4];
    const float* Wg   = (const float*)d_in[5];
    const float* Wb   = (const float*)d_in[6];
    const float* cq_w = (const float*)d_in[7];
    const float* cq_b = (const float*)d_in[8];
    const float* ck_w = (const float*)d_in[9];
    const float* ck_b = (const float*)d_in[10];
    const float* cv_w = (const float*)d_in[11];
    const float* cv_b = (const float*)d_in[12];
    const float* nw   = (const float*)d_in[13];
    float* out = (float*)d_out;

    cudaFuncSetAttribute(proj_mma, cudaFuncAttributeMaxDynamicSharedMemorySize, DSM_BYTES);
    cudaFuncSetAttribute(out_mma,  cudaFuncAttributeMaxDynamicSharedMemorySize, DSM_BYTES);

    split_x<<<BT, 256>>>(x);
    split_w<<<dim3(32, 32, 5), dim3(32, 32)>>>(Wq, Wk, Wv, Wg, Wo);

    proj_mma<<<dim3(DD / GBN, BT / GBM, 4), 256, DSM_BYTES>>>();

    beta_kernel<<<BT / 8, 256>>>(x, Wb);
    conv_norm<<<dim3(BT * 4, 1, 3), 256>>>(cq_w, cq_b, ck_w, ck_b, cv_w, cv_b);
    scan_kernel<<<BB * HH * 4, 256>>>();
    norm_gate<<<BT * 4, 256>>>(nw);

    out_mma<<<dim3(DD / GBN, BT / GBM), 256, DSM_BYTES>>>(out);
}

// round 15
// speedup vs baseline: 1.1002x; 1.0190x over previous
#include <cuda_runtime.h>
#include <cuda_bf16.h>
#include <cstdint>

// Problem constants
#define BB    2
#define TT    2048
#define DD    1024
#define HH    16
#define DH    64
#define BT    (BB*TT)          // 4096
#define KBIG  3072             // 3 * DD (split-in-K bf16 GEMM)
#define NELE  ((size_t)BT*DD)  // 4,194,304

// ---------------------------------------------------------------------------
// Scratch (no cudaMalloc allowed -> __device__ globals)
// ---------------------------------------------------------------------------
__device__ float g_qpre[NELE];
__device__ float g_kpre[NELE];
__device__ float g_vpre[NELE];
__device__ float g_gpre[NELE];
__device__ float g_qn[NELE];
__device__ float g_kn[NELE];
__device__ float g_vn[NELE];
__device__ float g_o[NELE];
__device__ float g_beta[BT*HH];
__device__ float g_bpre[(size_t)BT*128];   // beta pre-activation (cols 0..15 used)

// bf16 split operands for tensor-core GEMMs
__device__ __align__(16) __nv_bfloat16 g_Ax[(size_t)BT*KBIG];      // [Ah|Al|Ah] of x
__device__ __align__(16) __nv_bfloat16 g_Ao[(size_t)BT*KBIG];      // [Ah|Al|Ah] of o*gate
__device__ __align__(16) __nv_bfloat16 g_Bw[5][(size_t)DD*KBIG];   // W^T splits: [Bh|Bh|Bl]
__device__ __align__(16) __nv_bfloat16 g_Bwb[(size_t)128*KBIG];    // Wb^T split (16 rows + zeros)

// ---------------------------------------------------------------------------
// Small helpers
// ---------------------------------------------------------------------------
__device__ __forceinline__ uint32_t smem_u32(const void* p) {
    uint32_t a;
    asm("{ .reg .u64 t; cvta.to.shared.u64 t, %1; cvt.u32.u64 %0, t; }"
        : "=r"(a) : "l"(p));
    return a;
}
__device__ __forceinline__ unsigned sw128(unsigned o) { return o ^ ((o >> 3) & 0x70); }
__device__ __forceinline__ void cpa16(unsigned dst, const void* src) {
    asm volatile("cp.async.cg.shared.global [%0], [%1], 16;\n" ::"r"(dst), "l"(src));
}
__device__ __forceinline__ void ldsm4(uint32_t* r, uint32_t addr) {
    asm volatile("ldmatrix.sync.aligned.m8n8.x4.shared.b16 {%0,%1,%2,%3}, [%4];"
                 : "=r"(r[0]), "=r"(r[1]), "=r"(r[2]), "=r"(r[3]) : "r"(addr));
}
__device__ __forceinline__ void mma_bf16(float* d, const uint32_t* a, const uint32_t* b) {
    asm volatile(
        "mma.sync.aligned.m16n8k16.row.col.f32.bf16.bf16.f32 "
        "{%0,%1,%2,%3}, {%4,%5,%6,%7}, {%8,%9}, {%0,%1,%2,%3};"
        : "+f"(d[0]), "+f"(d[1]), "+f"(d[2]), "+f"(d[3])
        : "r"(a[0]), "r"(a[1]), "r"(a[2]), "r"(a[3]), "r"(b[0]), "r"(b[1]));
}

// ---------------------------------------------------------------------------
// Split kernels: x -> g_Ax ([hi|lo|hi]),  W -> W^T splits ([hi|hi|lo])
// ---------------------------------------------------------------------------
__global__ __launch_bounds__(256) void split_x(const float* __restrict__ x) {
    int row = blockIdx.x;
    int c0  = threadIdx.x * 4;
    float4 v = *(const float4*)(x + (size_t)row * DD + c0);
    float vv[4] = {v.x, v.y, v.z, v.w};
    size_t b = (size_t)row * KBIG + c0;
#pragma unroll
    for (int j = 0; j < 4; j++) {
        __nv_bfloat16 hi = __float2bfloat16(vv[j]);
        __nv_bfloat16 lo = __float2bfloat16(vv[j] - __bfloat162float(hi));
        g_Ax[b + j]          = hi;
        g_Ax[b + DD + j]     = lo;
        g_Ax[b + 2 * DD + j] = hi;
    }
}

__global__ __launch_bounds__(1024) void split_w(const float* __restrict__ Wq,
                                                const float* __restrict__ Wk,
                                                const float* __restrict__ Wv,
                                                const float* __restrict__ Wg,
                                                const float* __restrict__ Wo) {
    const float* W;
    switch (blockIdx.z) {
        case 0: W = Wq; break;
        case 1: W = Wk; break;
        case 2: W = Wv; break;
        case 3: W = Wg; break;
        default: W = Wo; break;
    }
    __nv_bfloat16* Bt = g_Bw[blockIdx.z];
    __shared__ float tile[32][33];
    int tx = threadIdx.x, ty = threadIdx.y;
    int k = blockIdx.y * 32 + ty, n = blockIdx.x * 32 + tx;
    tile[ty][tx] = W[(size_t)k * DD + n];
    __syncthreads();
    int nn = blockIdx.x * 32 + ty, kk = blockIdx.y * 32 + tx;
    float v = tile[tx][ty];  // = W[kk][nn]
    __nv_bfloat16 hi = __float2bfloat16(v);
    __nv_bfloat16 lo = __float2bfloat16(v - __bfloat162float(hi));
    size_t b = (size_t)nn * KBIG + kk;
    Bt[b]          = hi;
    Bt[b + DD]     = hi;
    Bt[b + 2 * DD] = lo;
}

// Wb (1024,16) -> g_Bwb rows 0..15 = [hi|hi|lo] of Wb columns; rows 16..127 zero.
__global__ __launch_bounds__(256) void split_wb(const float* __restrict__ Wb) {
    int n = blockIdx.x;  // 0..127
    __nv_bfloat16* row = g_Bwb + (size_t)n * KBIG;
    if (n < 16) {
        for (int k = threadIdx.x; k < DD; k += 256) {
            float v = Wb[(size_t)k * HH + n];
            __nv_bfloat16 hi = __float2bfloat16(v);
            __nv_bfloat16 lo = __float2bfloat16(v - __bfloat162float(hi));
            row[k]          = hi;
            row[k + DD]     = hi;
            row[k + 2 * DD] = lo;
        }
    } else {
        for (int k = threadIdx.x; k < KBIG; k += 256)
            row[k] = __float2bfloat16(0.f);
    }
}

// sigmoid on the 16 real beta columns
__global__ __launch_bounds__(256) void beta_sig() {
    int idx = blockIdx.x * 256 + threadIdx.x;   // 0..65535
    int bt = idx >> 4, h = idx & 15;
    float v = g_bpre[(size_t)bt * 128 + h];
    g_beta[(size_t)bt * HH + h] = 1.f / (1.f + expf(-v));
}

// ---------------------------------------------------------------------------
// bf16 tensor-core GEMM via mma.sync (portable HMMA; tcgen05 PTX rejected by
// this harness's .target sm_103).
// C[M,N] = A[M,KBIG] * Bt[N,KBIG]^T, fp32 out, row stride ldc.
// CTA tile 128x128, BK=64, SW128 smem, 3-stage cp.async ring.
// ONE barrier per stage; loads for stage i+2 issued BEFORE compute of stage i
// (write slot (i+2)%3 == slot read at i-1, whose readers passed this sync).
// __launch_bounds__(256,2): 2 CTAs/SM (2x99KB smem fits 228KB).
// ---------------------------------------------------------------------------
#define GBM   128
#define GBN   128
#define GBK   64
#define NSTG  3
#define NS    (KBIG/GBK)            // 48
#define STG_A (GBM*128)             // 16384 B
#define STG_B (GBN*128)             // 16384 B
#define STG_BYTES (STG_A + STG_B)   // 32768 B
#define DSM_BYTES (NSTG*STG_BYTES + 1024)

__device__ __forceinline__ void gemm_mma_body(const __nv_bfloat16* __restrict__ A,
                                              const __nv_bfloat16* __restrict__ Bt,
                                              float* __restrict__ C, int ldc) {
    extern __shared__ char dynsm[];
    const uint32_t smb = (smem_u32(dynsm) + 1023u) & ~1023u;
    const int tid = threadIdx.x;
    const int wid = tid >> 5, lid = tid & 31;
    const int bm = blockIdx.y * GBM;
    const int bn = blockIdx.x * GBN;
    const int wm = (wid & 3) * 32;
    const int wn = (wid >> 2) * 64;

    float acc[2][8][4];
#pragma unroll
    for (int i = 0; i < 2; i++)
#pragma unroll
        for (int j = 0; j < 8; j++)
#pragma unroll
            for (int q = 0; q < 4; q++) acc[i][j][q] = 0.f;

    auto load_stage = [&](int st, int slot) {
        unsigned baseA = smb + slot * STG_BYTES;
        unsigned baseB = baseA + STG_A;
        const __nv_bfloat16* Ab = A + (size_t)bm * KBIG + st * GBK;
        const __nv_bfloat16* Bb = Bt + (size_t)bn * KBIG + st * GBK;
#pragma unroll
        for (int c = tid; c < 1024; c += 256) {
            int r = c >> 3, ci = c & 7;
            cpa16(baseA + sw128(r * 128 + ci * 16), Ab + (size_t)r * KBIG + ci * 8);
        }
#pragma unroll
        for (int c = tid; c < 1024; c += 256) {
            int r = c >> 3, ci = c & 7;
            cpa16(baseB + sw128(r * 128 + ci * 16), Bb + (size_t)r * KBIG + ci * 8);
        }
    };

    // ldmatrix lane-address components (verified layout)
    const int a_row = (lid & 15);
    const int a_kb  = (lid >> 4) * 16;
    const int b_row = (lid & 7) + (lid >> 4) * 8;
    const int b_kb  = ((lid >> 3) & 1) * 16;

    load_stage(0, 0);
    asm volatile("cp.async.commit_group;\n" ::: "memory");
    load_stage(1, 1);
    asm volatile("cp.async.commit_group;\n" ::: "memory");

    for (int i = 0; i < NS; i++) {
        const int slot = i % NSTG;
        asm volatile("cp.async.wait_group 1;\n" ::: "memory");
        __syncthreads();

        // issue next stage's loads FIRST so they overlap the whole compute
        if (i + 2 < NS) load_stage(i + 2, (i + 2) % NSTG);
        asm volatile("cp.async.commit_group;\n" ::: "memory");

        const unsigned baseA = smb + slot * STG_BYTES;
        const unsigned baseB = baseA + STG_A;

#pragma unroll
        for (int ks = 0; ks < 4; ks++) {
            uint32_t af[2][4];
#pragma unroll
            for (int mt = 0; mt < 2; mt++)
                ldsm4(af[mt],
                      baseA + sw128((wm + mt * 16 + a_row) * 128 + ks * 32 + a_kb));
            uint32_t bfr[4][4];
#pragma unroll
            for (int nt = 0; nt < 4; nt++)
                ldsm4(bfr[nt],
                      baseB + sw128((wn + nt * 16 + b_row) * 128 + ks * 32 + b_kb));
#pragma unroll
            for (int mt = 0; mt < 2; mt++)
#pragma unroll
                for (int n8 = 0; n8 < 8; n8++)
                    mma_bf16(acc[mt][n8], af[mt], &bfr[n8 >> 1][(n8 & 1) * 2]);
        }
    }

    // Epilogue
    const int g   = lid >> 2;
    const int tig = lid & 3;
#pragma unroll
    for (int mt = 0; mt < 2; mt++) {
#pragma unroll
        for (int n8 = 0; n8 < 8; n8++) {
            int row = bm + wm + mt * 16 + g;
            int col = bn + wn + n8 * 8 + tig * 2;
            float2 lo = make_float2(acc[mt][n8][0], acc[mt][n8][1]);
            float2 hi = make_float2(acc[mt][n8][2], acc[mt][n8][3]);
            *(float2*)(C + (size_t)row * ldc + col)       = lo;
            *(float2*)(C + (size_t)(row + 8) * ldc + col) = hi;
        }
    }
}

// z = 0..3: q/k/v/g projections (N=1024). z = 4: beta slice (N=128, x-tile 0 only).
__global__ __launch_bounds__(256, 2) void proj_mma() {
    if (blockIdx.z == 4) {
        if (blockIdx.x != 0) return;
        gemm_mma_body(g_Ax, g_Bwb, g_bpre, 128);
        return;
    }
    float* C;
    switch (blockIdx.z) {
        case 0:  C = g_qpre; break;
        case 1:  C = g_kpre; break;
        case 2:  C = g_vpre; break;
        default: C = g_gpre; break;
    }
    gemm_mma_body(g_Ax, g_Bw[blockIdx.z], C, DD);
}

__global__ __launch_bounds__(256, 2) void out_mma(float* __restrict__ out) {
    gemm_mma_body(g_Ao, g_Bw[4], out, DD);
}

// ---------------------------------------------------------------------------
// Depthwise causal conv(k=4) + bias + silu, then (for q,k) per-head l2norm.
// Fused: blockIdx.z = mode (0=q, 1=k, 2=v) -> single launch, modes overlap.
// ---------------------------------------------------------------------------
__global__ __launch_bounds__(256) void conv_norm(const float* __restrict__ cq_w,
                                                 const float* __restrict__ cq_b,
                                                 const float* __restrict__ ck_w,
                                                 const float* __restrict__ ck_b,
                                                 const float* __restrict__ cv_w,
                                                 const float* __restrict__ cv_b) {
    int mode = blockIdx.z;
    const float* pre = (mode == 0) ? g_qpre : (mode == 1) ? g_kpre : g_vpre;
    float* out       = (mode == 0) ? g_qn   : (mode == 1) ? g_kn   : g_vn;
    const float* cw  = (mode == 0) ? cq_w   : (mode == 1) ? ck_w   : cv_w;
    const float* cb  = (mode == 0) ? cq_b   : (mode == 1) ? ck_b   : cv_b;

    int blk = blockIdx.x;
    int hq  = blk & 3;
    int bt  = blk >> 2;
    int t   = bt & (TT - 1);
    int b   = bt >> 11;
    int tid = threadIdx.x;
    int hh  = tid >> 6;
    int ch  = hq * 256 + tid;

    float acc = cb[ch];
#pragma unroll
    for (int j = 0; j < 4; j++) {
        int tt = t - 3 + j;
        if (tt >= 0)
            acc = fmaf(pre[(size_t)(b * TT + tt) * DD + ch], cw[ch * 4 + j], acc);
    }
    float y = acc / (1.f + expf(-acc));  // silu

    if (mode < 2) {
        float ss = y * y;
#pragma unroll
        for (int m = 16; m; m >>= 1) ss += __shfl_xor_sync(0xffffffffu, ss, m);
        __shared__ float red[8];
        if ((tid & 31) == 0) red[tid >> 5] = ss;
        __syncthreads();
        float tot = red[hh * 2] + red[hh * 2 + 1];
        float inv = rsqrtf(tot + 1e-6f);
        if (mode == 0) inv *= 0.125f;
        y *= inv;
    }
    out[(size_t)bt * DD + ch] = y;
}

// ---------------------------------------------------------------------------
// Sequential delta-rule scan. Triple-buffered cp.async, ONE barrier per step.
// Fused reduction: p=k.S_old, po=q.S_old, qk=q.k reduced concurrently;
// o = po + qk*err.
// ---------------------------------------------------------------------------
__device__ __forceinline__ void cpa4(void* smem, const void* g) {
    unsigned sa = (unsigned)__cvta_generic_to_shared(smem);
    asm volatile("cp.async.ca.shared.global [%0], [%1], 4;\n" ::"r"(sa), "l"(g));
}

__global__ __launch_bounds__(256) void scan_kernel() {
    int blk = blockIdx.x;
    int sv  = blk & 3;
    int bh  = blk >> 2;
    int b   = bh >> 4, h = bh & 15;
    int v0  = sv * 16;
    int tid = threadIdx.x;
    int g   = tid & 15;
    int vl  = tid >> 4;

    __shared__ __align__(16) float buf[3][160];

    const size_t base = (size_t)b * TT * DD + h * DH;
    const float* Kp = g_kn + base;
    const float* Qp = g_qn + base;
    const float* Vp = g_vn + base + v0;
    const float* Bp = g_beta + (size_t)b * TT * HH + h;
    float* Op = g_o + base + v0;

    auto issue = [&](int t, int pb) {
        if (tid < 64)        cpa4(&buf[pb][tid], Kp + (size_t)t * DD + tid);
        else if (tid < 128)  cpa4(&buf[pb][tid], Qp + (size_t)t * DD + (tid - 64));
        else if (tid < 144)  cpa4(&buf[pb][tid], Vp + (size_t)t * DD + (tid - 128));
        else if (tid == 144) cpa4(&buf[pb][144], Bp + (size_t)t * HH);
    };

    issue(0, 0);
    asm volatile("cp.async.commit_group;\n" ::: "memory");
    issue(1, 1);
    asm volatile("cp.async.commit_group;\n" ::: "memory");

    float s0 = 0.f, s1 = 0.f, s2 = 0.f, s3 = 0.f;
    int pb = 0;

    for (int t = 0; t < TT; t++) {
        asm volatile("cp.async.wait_group 1;\n" ::: "memory");
        __syncthreads();

        float4 kv = *(const float4*)&buf[pb][g * 4];
        float4 qv = *(const float4*)&buf[pb][64 + g * 4];
        float  vt = buf[pb][128 + vl];
        float  bt = buf[pb][144];

        float p  = fmaf(kv.x, s0, fmaf(kv.y, s1, fmaf(kv.z, s2, kv.w * s3)));
        float po = fmaf(qv.x, s0, fmaf(qv.y, s1, fmaf(qv.z, s2, qv.w * s3)));
        float qk = fmaf(qv.x, kv.x, fmaf(qv.y, kv.y,
                        fmaf(qv.z, kv.z, qv.w * kv.w)));
#pragma unroll
        for (int m = 1; m <= 8; m <<= 1) {
            p  += __shfl_xor_sync(0xffffffffu, p,  m);
            po += __shfl_xor_sync(0xffffffffu, po, m);
            qk += __shfl_xor_sync(0xffffffffu, qk, m);
        }

        float err = (vt - p) * bt;
        float o   = fmaf(qk, err, po);
        if (g == 0) Op[(size_t)t * DD + vl] = o;

        s0 = fmaf(kv.x, err, s0);
        s1 = fmaf(kv.y, err, s1);
        s2 = fmaf(kv.z, err, s2);
        s3 = fmaf(kv.w, err, s3);

        if (t + 2 < TT) issue(t + 2, (t + 2) % 3);
        asm volatile("cp.async.commit_group;\n" ::: "memory");

        pb = (pb == 2) ? 0 : pb + 1;
    }
}

// ---------------------------------------------------------------------------
// RMSNorm over head_dim + silu gate -> bf16 split rows of g_Ao
// ---------------------------------------------------------------------------
__global__ __launch_bounds__(256) void norm_gate(const float* __restrict__ nw) {
    int blk = blockIdx.x;
    int hq  = blk & 3;
    int bt  = blk >> 2;
    int tid = threadIdx.x;
    int hh  = tid >> 6;
    int c   = tid & 63;
    int ch  = hq * 256 + tid;
    size_t idx = (size_t)bt * DD + ch;

    float o  = g_o[idx];
    float ss = o * o;
#pragma unroll
    for (int m = 16; m; m >>= 1) ss += __shfl_xor_sync(0xffffffffu, ss, m);
    __shared__ float red[8];
    if ((tid & 31) == 0) red[tid >> 5] = ss;
    __syncthreads();
    float tot = red[hh * 2] + red[hh * 2 + 1];
    float inv = rsqrtf(tot * (1.f / 64.f) + 1e-5f);
    o *= inv * nw[c];
    float gt = g_gpre[idx];
    o *= gt / (1.f + expf(-gt));

    __nv_bfloat16 hi = __float2bfloat16(o);
    __nv_bfloat16 lo = __float2bfloat16(o - __bfloat162float(hi));
    size_t b = (size_t)bt * KBIG + ch;
    g_Ao[b]          = hi;
    g_Ao[b + DD]     = lo;
    g_Ao[b + 2 * DD] = hi;
}

// ---------------------------------------------------------------------------
// Launch: x Wq Wk Wv Wo Wg Wb cq_w cq_b ck_w ck_b cv_w cv_b nw
// ---------------------------------------------------------------------------
extern "C" void kernel_launch(void* const* d_in, const int* in_sizes, int n_in,
                              void* d_out, int out_size) {
    const float* x    = (const float*)d_in[0];
    const float* Wq   = (const float*)d_in[1];
    const float* Wk   = (const float*)d_in[2];
    const float* Wv   = (const float*)d_in[3];
    const float* Wo   = (const float*)d_in[4];
    const float* Wg   = (const float*)d_in[5];
    const float* Wb   = (const float*)d_in[6];
    const float* cq_w = (const float*)d_in[7];
    const float* cq_b = (const float*)d_in[8];
    const float* ck_w = (const float*)d_in[9];
    const float* ck_b = (const float*)d_in[10];
    const float* cv_w = (const float*)d_in[11];
    const float* cv_b = (const float*)d_in[12];
    const float* nw   = (const float*)d_in[13];
    float* out = (float*)d_out;

    cudaFuncSetAttribute(proj_mma, cudaFuncAttributeMaxDynamicSharedMemorySize, DSM_BYTES);
    cudaFuncSetAttribute(out_mma,  cudaFuncAttributeMaxDynamicSharedMemorySize, DSM_BYTES);

    split_x<<<BT, 256>>>(x);
    split_w<<<dim3(32, 32, 5), dim3(32, 32)>>>(Wq, Wk, Wv, Wg, Wo);
    split_wb<<<128, 256>>>(Wb);

    // z 0..3: projections; z 4: beta slice (only x-tile 0 active)
    proj_mma<<<dim3(DD / GBN, BT / GBM, 5), 256, DSM_BYTES>>>();
    beta_sig<<<BT * HH / 256, 256>>>();

    conv_norm<<<dim3(BT * 4, 1, 3), 256>>>(cq_w, cq_b, ck_w, ck_b, cv_w, cv_b);
    scan_kernel<<<BB * HH * 4, 256>>>();
    norm_gate<<<BT * 4, 256>>>(nw);

    out_mma<<<dim3(DD / GBN, BT / GBM), 256, DSM_BYTES>>>(out);
}